// round 3
// baseline (speedup 1.0000x reference)
#include <cuda_runtime.h>
#include <math.h>

// Problem constants (shapes fixed by the dataset)
#define NN 50000
#define NE 800000
#define D0 64   // x features
#define D1 96   // hidden
#define D2 64   // out

// ---------------- scratch (device globals: no allocation allowed) ----------
__device__ int   g_is64;
__device__ int   g_csr[NE];
__device__ int   g_cnt[NN];
__device__ int   g_row[NN + 1];
__device__ int   g_cur[NN];
__device__ float g_dis[NN];
__device__ float g_hs1[NN * D1];  // (x@W1)*dis[row]
__device__ float g_h  [NN * D1];  // relu(layer1)
__device__ float g_hs2[NN * D2];  // (h@W2)*dis[row]

// ---------------- launch 0: zero histogram + dtype detect ------------------
// Values are in [0, 50000): if the buffer is little-endian int64, every odd
// 32-bit word of the first 1024 entries is 0. For int32 those words are
// random edge ids; P(all zero) ~ (1/50000)^1024 ~ 0.
__global__ void k_setup(const int* __restrict__ e) {
    if (blockIdx.x < 196) {
        int i = blockIdx.x * 256 + threadIdx.x;
        if (i < NN) g_cnt[i] = 0;
    } else {
        __shared__ int nz;
        if (threadIdx.x == 0) nz = 0;
        __syncthreads();
        int local = 0;
        for (int i = threadIdx.x; i < 1024; i += 256) local |= e[2 * i + 1];
        if (local) atomicOr(&nz, 1);
        __syncthreads();
        if (threadIdx.x == 0) g_is64 = (nz == 0) ? 1 : 0;
    }
}

// ---------------- launch 1: in-degree histogram (2 edges / thread) ---------
__global__ void k_hist(const void* __restrict__ ep) {
    int i = blockIdx.x * blockDim.x + threadIdx.x;  // pair index
    if (i >= NE / 2) return;
    int d0, d1;
    if (g_is64) {
        const longlong2* p = (const longlong2*)ep;   // 2*NE int64 = NE ll2
        longlong2 dd = p[NE / 2 + i];                // dst half
        d0 = (int)dd.x; d1 = (int)dd.y;
    } else {
        const int2* p = (const int2*)ep;             // 2*NE int32 = NE int2
        int2 dd = p[NE / 2 + i];
        d0 = dd.x; d1 = dd.y;
    }
    atomicAdd(&g_cnt[d0], 1);   // result unused -> REDG
    atomicAdd(&g_cnt[d1], 1);
}

// ---------------- launch 2: exclusive scan + dis ---------------------------
// Single-block scan of g_cnt -> g_row / g_cur, plus g_dis = rsqrt(deg+1).
__global__ void k_scan_dis() {
    __shared__ int sums[1024];
    const int CH = (NN + 1023) / 1024;  // 49
    int t = threadIdx.x;
    int base = t * CH;
    int s = 0;
    for (int i = 0; i < CH; i++) {
        int idx = base + i;
        if (idx < NN) s += g_cnt[idx];
    }
    sums[t] = s;
    __syncthreads();
    for (int off = 1; off < 1024; off <<= 1) {
        int v = sums[t];
        int add = (t >= off) ? sums[t - off] : 0;
        __syncthreads();
        sums[t] = v + add;
        __syncthreads();
    }
    int run = (t == 0) ? 0 : sums[t - 1];
    for (int i = 0; i < CH; i++) {
        int idx = base + i;
        if (idx < NN) {
            int c = g_cnt[idx];
            g_row[idx] = run;
            g_cur[idx] = run;
            g_dis[idx] = rsqrtf((float)c + 1.0f);
            run += c;
        }
    }
    if (t == 1023) g_row[NN] = sums[1023];
}

// ---------------- launch 3: CSR scatter (profiling target this round) ------
__global__ void k_scatter(const void* __restrict__ ep) {
    int e = blockIdx.x * blockDim.x + threadIdx.x;
    if (e >= NE) return;
    int s, d;
    if (g_is64) {
        const long long* p = (const long long*)ep;
        s = (int)p[e];
        d = (int)p[NE + e];
    } else {
        const int* p = (const int*)ep;
        s = p[e];
        d = p[NE + e];
    }
    int pos = atomicAdd(&g_cur[d], 1);
    g_csr[pos] = s;
}

// ---------------- GEMM: HS[row][c] = dis[row] * sum_k X[row][k]*W[k][c] -----
// 256 threads = 8 warps, 32 rows per block (4 rows/warp); W and 32 X rows in
// shared. Lane l computes columns l, l+32, (l+64). Conflict-free LDS.
template <int IN, int OUT>
__global__ void k_gemm(const float* __restrict__ X, const float* __restrict__ W,
                       float* __restrict__ HS) {
    constexpr int CPL = OUT / 32;
    __shared__ float Ws[IN * OUT];
    __shared__ float Xs[32 * IN];
    int t = threadIdx.x;
    for (int i = t; i < IN * OUT; i += 256) Ws[i] = W[i];
    int row0 = blockIdx.x * 32;
    for (int i = t; i < 32 * IN; i += 256) {
        int r = i / IN, k = i % IN;
        int gr = row0 + r;
        Xs[i] = (gr < NN) ? X[gr * IN + k] : 0.0f;
    }
    __syncthreads();

    int w = t >> 5, lane = t & 31;
    int rbase = w * 4;
    float acc[4][CPL];
#pragma unroll
    for (int r = 0; r < 4; r++)
#pragma unroll
        for (int c = 0; c < CPL; c++) acc[r][c] = 0.0f;

#pragma unroll 8
    for (int k = 0; k < IN; k++) {
        float wv[CPL];
#pragma unroll
        for (int c = 0; c < CPL; c++) wv[c] = Ws[k * OUT + lane + 32 * c];
#pragma unroll
        for (int r = 0; r < 4; r++) {
            float xv = Xs[(rbase + r) * IN + k];
#pragma unroll
            for (int c = 0; c < CPL; c++) acc[r][c] = fmaf(xv, wv[c], acc[r][c]);
        }
    }

#pragma unroll
    for (int r = 0; r < 4; r++) {
        int gr = row0 + rbase + r;
        if (gr < NN) {
            float d = g_dis[gr];
#pragma unroll
            for (int c = 0; c < CPL; c++)
                HS[gr * OUT + lane + 32 * c] = acc[r][c] * d;
        }
    }
}

// ---------------- Aggregation: one warp per node, vectorized gathers -------
// out[i][f] = act( dis[i]*(HS[i][f] + sum_{e: dst=i} HS[src_e][f]) + b[f] )
// F=96: float4 gathers, lanes 0..23 active (1 LDG.128 per edge).
// F=64: float2 gathers, all 32 lanes     (1 LDG.64  per edge).
__device__ __forceinline__ float act_relu(float v)    { return fmaxf(v, 0.0f); }
__device__ __forceinline__ float act_sigmoid(float v) { return 1.0f / (1.0f + expf(-v)); }

template <int F, int ACT>
__global__ void k_agg(const float* __restrict__ HS, const float* __restrict__ b,
                      float* __restrict__ OUT) {
    int warp = (blockIdx.x * blockDim.x + threadIdx.x) >> 5;
    int lane = threadIdx.x & 31;
    if (warp >= NN) return;

    int beg = g_row[warp], end = g_row[warp + 1];

    if constexpr (F == 96) {
        constexpr int C4 = F / 4;  // 24 float4 columns
        const float4* H4 = (const float4*)HS;
        bool on = lane < C4;
        float4 acc = make_float4(0.f, 0.f, 0.f, 0.f);
        if (on) acc = H4[warp * C4 + lane];  // self loop

        int j = beg;
        for (; j + 3 < end; j += 4) {
            int s0 = g_csr[j + 0], s1 = g_csr[j + 1];
            int s2 = g_csr[j + 2], s3 = g_csr[j + 3];
            if (on) {
                float4 v0 = H4[s0 * C4 + lane];
                float4 v1 = H4[s1 * C4 + lane];
                float4 v2 = H4[s2 * C4 + lane];
                float4 v3 = H4[s3 * C4 + lane];
                acc.x += (v0.x + v1.x) + (v2.x + v3.x);
                acc.y += (v0.y + v1.y) + (v2.y + v3.y);
                acc.z += (v0.z + v1.z) + (v2.z + v3.z);
                acc.w += (v0.w + v1.w) + (v2.w + v3.w);
            }
        }
        for (; j < end; j++) {
            int s0 = g_csr[j];
            if (on) {
                float4 v = H4[s0 * C4 + lane];
                acc.x += v.x; acc.y += v.y; acc.z += v.z; acc.w += v.w;
            }
        }
        if (on) {
            float d = g_dis[warp];
            float4 bb = ((const float4*)b)[lane];
            float4 o;
            if (ACT == 0) {
                o.x = act_relu(fmaf(d, acc.x, bb.x));
                o.y = act_relu(fmaf(d, acc.y, bb.y));
                o.z = act_relu(fmaf(d, acc.z, bb.z));
                o.w = act_relu(fmaf(d, acc.w, bb.w));
            } else {
                o.x = act_sigmoid(fmaf(d, acc.x, bb.x));
                o.y = act_sigmoid(fmaf(d, acc.y, bb.y));
                o.z = act_sigmoid(fmaf(d, acc.z, bb.z));
                o.w = act_sigmoid(fmaf(d, acc.w, bb.w));
            }
            ((float4*)OUT)[warp * C4 + lane] = o;
        }
    } else {  // F == 64
        constexpr int C2 = F / 2;  // 32 float2 columns, all lanes active
        const float2* H2 = (const float2*)HS;
        float2 acc = H2[warp * C2 + lane];  // self loop

        int j = beg;
        for (; j + 3 < end; j += 4) {
            int s0 = g_csr[j + 0], s1 = g_csr[j + 1];
            int s2 = g_csr[j + 2], s3 = g_csr[j + 3];
            float2 v0 = H2[s0 * C2 + lane];
            float2 v1 = H2[s1 * C2 + lane];
            float2 v2 = H2[s2 * C2 + lane];
            float2 v3 = H2[s3 * C2 + lane];
            acc.x += (v0.x + v1.x) + (v2.x + v3.x);
            acc.y += (v0.y + v1.y) + (v2.y + v3.y);
        }
        for (; j < end; j++) {
            int s0 = g_csr[j];
            float2 v = H2[s0 * C2 + lane];
            acc.x += v.x; acc.y += v.y;
        }
        float d = g_dis[warp];
        float2 bb = ((const float2*)b)[lane];
        float2 o;
        if (ACT == 0) {
            o.x = act_relu(fmaf(d, acc.x, bb.x));
            o.y = act_relu(fmaf(d, acc.y, bb.y));
        } else {
            o.x = act_sigmoid(fmaf(d, acc.x, bb.x));
            o.y = act_sigmoid(fmaf(d, acc.y, bb.y));
        }
        ((float2*)OUT)[warp * C2 + lane] = o;
    }
}

// ---------------- launch ---------------------------------------------------
extern "C" void kernel_launch(void* const* d_in, const int* in_sizes, int n_in,
                              void* d_out, int out_size) {
    const float* x  = (const float*)d_in[0];
    const void*  ei = d_in[1];
    const float* W1 = (const float*)d_in[2];
    const float* b1 = (const float*)d_in[3];
    const float* W2 = (const float*)d_in[4];
    const float* b2 = (const float*)d_in[5];
    float* out = (float*)d_out;

    const int TB = 256;
    // 0..3: graph/CSR construction (scatter lands at index 3 -> ncu target)
    k_setup<<<197, 256>>>((const int*)ei);
    k_hist<<<(NE / 2 + TB - 1) / TB, TB>>>(ei);
    k_scan_dis<<<1, 1024>>>();
    k_scatter<<<(NE + TB - 1) / TB, TB>>>(ei);

    // 4..5: layer 1
    k_gemm<D0, D1><<<(NN + 31) / 32, 256>>>(x, W1, g_hs1);
    k_agg<D1, 0><<<(NN * 32 + TB - 1) / TB, TB>>>(g_hs1, b1, g_h);

    // 6..7: layer 2
    k_gemm<D1, D2><<<(NN + 31) / 32, 256>>>(g_h, W2, g_hs2);
    k_agg<D2, 1><<<(NN * 32 + TB - 1) / TB, TB>>>(g_hs2, b2, out);
}

// round 4
// speedup vs baseline: 1.0032x; 1.0032x over previous
#include <cuda_runtime.h>
#include <math.h>

// Problem constants (shapes fixed by the dataset)
#define NN 50000
#define NE 800000
#define D0 64   // x features
#define D1 96   // hidden
#define D2 64   // out

// ---------------- scratch (device globals: no allocation allowed) ----------
__device__ int   g_is64;
__device__ int   g_csr[NE];
__device__ int   g_cnt[NN];
__device__ int   g_row[NN + 1];
__device__ int   g_cur[NN];
__device__ float g_dis[NN];
__device__ float g_hs1[NN * D1];  // (x@W1)*dis[row]
__device__ float g_h  [NN * D1];  // relu(layer1)
__device__ float g_hs2[NN * D2];  // (h@W2)*dis[row]

// ---------------- launch 0: zero histogram + dtype detect ------------------
// Values are in [0, 50000): if the buffer is little-endian int64, every odd
// 32-bit word of the first 1024 entries is 0. For int32 those words are
// random edge ids; P(all zero) ~ (1/50000)^1024 ~ 0.
__global__ void k_setup(const int* __restrict__ e) {
    if (blockIdx.x < 196) {
        int i = blockIdx.x * 256 + threadIdx.x;
        if (i < NN) g_cnt[i] = 0;
    } else {
        __shared__ int nz;
        if (threadIdx.x == 0) nz = 0;
        __syncthreads();
        int local = 0;
        for (int i = threadIdx.x; i < 1024; i += 256) local |= e[2 * i + 1];
        if (local) atomicOr(&nz, 1);
        __syncthreads();
        if (threadIdx.x == 0) g_is64 = (nz == 0) ? 1 : 0;
    }
}

// ---------------- launch 1: in-degree histogram (2 edges / thread) ---------
__global__ void k_hist(const void* __restrict__ ep) {
    int i = blockIdx.x * blockDim.x + threadIdx.x;  // pair index
    if (i >= NE / 2) return;
    int d0, d1;
    if (g_is64) {
        const longlong2* p = (const longlong2*)ep;   // 2*NE int64 = NE ll2
        longlong2 dd = p[NE / 2 + i];                // dst half
        d0 = (int)dd.x; d1 = (int)dd.y;
    } else {
        const int2* p = (const int2*)ep;             // 2*NE int32 = NE int2
        int2 dd = p[NE / 2 + i];
        d0 = dd.x; d1 = dd.y;
    }
    atomicAdd(&g_cnt[d0], 1);   // result unused -> REDG
    atomicAdd(&g_cnt[d1], 1);
}

// ---------------- launch 2: exclusive scan + dis ---------------------------
__global__ void k_scan_dis() {
    __shared__ int sums[1024];
    const int CH = (NN + 1023) / 1024;  // 49
    int t = threadIdx.x;
    int base = t * CH;
    int s = 0;
    for (int i = 0; i < CH; i++) {
        int idx = base + i;
        if (idx < NN) s += g_cnt[idx];
    }
    sums[t] = s;
    __syncthreads();
    for (int off = 1; off < 1024; off <<= 1) {
        int v = sums[t];
        int add = (t >= off) ? sums[t - off] : 0;
        __syncthreads();
        sums[t] = v + add;
        __syncthreads();
    }
    int run = (t == 0) ? 0 : sums[t - 1];
    for (int i = 0; i < CH; i++) {
        int idx = base + i;
        if (idx < NN) {
            int c = g_cnt[idx];
            g_row[idx] = run;
            g_cur[idx] = run;
            g_dis[idx] = rsqrtf((float)c + 1.0f);
            run += c;
        }
    }
    if (t == 1023) g_row[NN] = sums[1023];
}

// ---------------- GEMM: HS[row][c] = dis[row] * sum_k X[row][k]*W[k][c] -----
// 256 threads = 8 warps, 32 rows per block (4 rows/warp); W and 32 X rows in
// shared. Lane l computes columns l, l+32, (l+64). Conflict-free LDS.
template <int IN, int OUT>
__global__ void k_gemm(const float* __restrict__ X, const float* __restrict__ W,
                       float* __restrict__ HS) {
    constexpr int CPL = OUT / 32;
    __shared__ float Ws[IN * OUT];
    __shared__ float Xs[32 * IN];
    int t = threadIdx.x;
    for (int i = t; i < IN * OUT; i += 256) Ws[i] = W[i];
    int row0 = blockIdx.x * 32;
    for (int i = t; i < 32 * IN; i += 256) {
        int r = i / IN, k = i % IN;
        int gr = row0 + r;
        Xs[i] = (gr < NN) ? X[gr * IN + k] : 0.0f;
    }
    __syncthreads();

    int w = t >> 5, lane = t & 31;
    int rbase = w * 4;
    float acc[4][CPL];
#pragma unroll
    for (int r = 0; r < 4; r++)
#pragma unroll
        for (int c = 0; c < CPL; c++) acc[r][c] = 0.0f;

#pragma unroll
    for (int k = 0; k < IN; k++) {
        float wv[CPL];
#pragma unroll
        for (int c = 0; c < CPL; c++) wv[c] = Ws[k * OUT + lane + 32 * c];
        float xv[4];
#pragma unroll
        for (int r = 0; r < 4; r++) xv[r] = Xs[(rbase + r) * IN + k];
#pragma unroll
        for (int r = 0; r < 4; r++)
#pragma unroll
            for (int c = 0; c < CPL; c++) acc[r][c] = fmaf(xv[r], wv[c], acc[r][c]);
    }

#pragma unroll
    for (int r = 0; r < 4; r++) {
        int gr = row0 + rbase + r;
        if (gr < NN) {
            float d = g_dis[gr];
#pragma unroll
            for (int c = 0; c < CPL; c++)
                HS[gr * OUT + lane + 32 * c] = acc[r][c] * d;
        }
    }
}

// ---------------- launch 4: CSR scatter ------------------------------------
__global__ void k_scatter(const void* __restrict__ ep) {
    int e = blockIdx.x * blockDim.x + threadIdx.x;
    if (e >= NE) return;
    int s, d;
    if (g_is64) {
        const long long* p = (const long long*)ep;
        s = (int)p[e];
        d = (int)p[NE + e];
    } else {
        const int* p = (const int*)ep;
        s = p[e];
        d = p[NE + e];
    }
    int pos = atomicAdd(&g_cur[d], 1);
    g_csr[pos] = s;
}

// ---------------- Aggregation: one warp per node, vectorized gathers -------
// out[i][f] = act( dis[i]*(HS[i][f] + sum_{e: dst=i} HS[src_e][f]) + b[f] )
__device__ __forceinline__ float act_relu(float v)    { return fmaxf(v, 0.0f); }
__device__ __forceinline__ float act_sigmoid(float v) { return 1.0f / (1.0f + expf(-v)); }

template <int F, int ACT>
__global__ void k_agg(const float* __restrict__ HS, const float* __restrict__ b,
                      float* __restrict__ OUT) {
    int warp = (blockIdx.x * blockDim.x + threadIdx.x) >> 5;
    int lane = threadIdx.x & 31;
    if (warp >= NN) return;

    int beg = g_row[warp], end = g_row[warp + 1];

    if constexpr (F == 96) {
        constexpr int C4 = F / 4;  // 24 float4 columns
        const float4* H4 = (const float4*)HS;
        bool on = lane < C4;
        float4 acc = make_float4(0.f, 0.f, 0.f, 0.f);
        if (on) acc = H4[warp * C4 + lane];  // self loop

        int j = beg;
        for (; j + 3 < end; j += 4) {
            int s0 = g_csr[j + 0], s1 = g_csr[j + 1];
            int s2 = g_csr[j + 2], s3 = g_csr[j + 3];
            if (on) {
                float4 v0 = H4[s0 * C4 + lane];
                float4 v1 = H4[s1 * C4 + lane];
                float4 v2 = H4[s2 * C4 + lane];
                float4 v3 = H4[s3 * C4 + lane];
                acc.x += (v0.x + v1.x) + (v2.x + v3.x);
                acc.y += (v0.y + v1.y) + (v2.y + v3.y);
                acc.z += (v0.z + v1.z) + (v2.z + v3.z);
                acc.w += (v0.w + v1.w) + (v2.w + v3.w);
            }
        }
        for (; j < end; j++) {
            int s0 = g_csr[j];
            if (on) {
                float4 v = H4[s0 * C4 + lane];
                acc.x += v.x; acc.y += v.y; acc.z += v.z; acc.w += v.w;
            }
        }
        if (on) {
            float d = g_dis[warp];
            float4 bb = ((const float4*)b)[lane];
            float4 o;
            if (ACT == 0) {
                o.x = act_relu(fmaf(d, acc.x, bb.x));
                o.y = act_relu(fmaf(d, acc.y, bb.y));
                o.z = act_relu(fmaf(d, acc.z, bb.z));
                o.w = act_relu(fmaf(d, acc.w, bb.w));
            } else {
                o.x = act_sigmoid(fmaf(d, acc.x, bb.x));
                o.y = act_sigmoid(fmaf(d, acc.y, bb.y));
                o.z = act_sigmoid(fmaf(d, acc.z, bb.z));
                o.w = act_sigmoid(fmaf(d, acc.w, bb.w));
            }
            ((float4*)OUT)[warp * C4 + lane] = o;
        }
    } else {  // F == 64
        constexpr int C2 = F / 2;  // 32 float2 columns, all lanes active
        const float2* H2 = (const float2*)HS;
        float2 acc = H2[warp * C2 + lane];  // self loop

        int j = beg;
        for (; j + 3 < end; j += 4) {
            int s0 = g_csr[j + 0], s1 = g_csr[j + 1];
            int s2 = g_csr[j + 2], s3 = g_csr[j + 3];
            float2 v0 = H2[s0 * C2 + lane];
            float2 v1 = H2[s1 * C2 + lane];
            float2 v2 = H2[s2 * C2 + lane];
            float2 v3 = H2[s3 * C2 + lane];
            acc.x += (v0.x + v1.x) + (v2.x + v3.x);
            acc.y += (v0.y + v1.y) + (v2.y + v3.y);
        }
        for (; j < end; j++) {
            int s0 = g_csr[j];
            float2 v = H2[s0 * C2 + lane];
            acc.x += v.x; acc.y += v.y;
        }
        float d = g_dis[warp];
        float2 bb = ((const float2*)b)[lane];
        float2 o;
        if (ACT == 0) {
            o.x = act_relu(fmaf(d, acc.x, bb.x));
            o.y = act_relu(fmaf(d, acc.y, bb.y));
        } else {
            o.x = act_sigmoid(fmaf(d, acc.x, bb.x));
            o.y = act_sigmoid(fmaf(d, acc.y, bb.y));
        }
        ((float2*)OUT)[warp * C2 + lane] = o;
    }
}

// ---------------- launch ---------------------------------------------------
extern "C" void kernel_launch(void* const* d_in, const int* in_sizes, int n_in,
                              void* d_out, int out_size) {
    const float* x  = (const float*)d_in[0];
    const void*  ei = d_in[1];
    const float* W1 = (const float*)d_in[2];
    const float* b1 = (const float*)d_in[3];
    const float* W2 = (const float*)d_in[4];
    const float* b2 = (const float*)d_in[5];
    float* out = (float*)d_out;

    const int TB = 256;
    k_setup<<<197, 256>>>((const int*)ei);                      // 0
    k_hist<<<(NE / 2 + TB - 1) / TB, TB>>>(ei);                 // 1
    k_scan_dis<<<1, 1024>>>();                                  // 2
    k_gemm<D0, D1><<<(NN + 31) / 32, 256>>>(x, W1, g_hs1);      // 3  <- ncu probe
    k_scatter<<<(NE + TB - 1) / TB, TB>>>(ei);                  // 4
    k_agg<D1, 0><<<(NN * 32 + TB - 1) / TB, TB>>>(g_hs1, b1, g_h);   // 5
    k_gemm<D1, D2><<<(NN + 31) / 32, 256>>>(g_h, W2, g_hs2);    // 6
    k_agg<D2, 1><<<(NN * 32 + TB - 1) / TB, TB>>>(g_hs2, b2, out);   // 7
}